// round 14
// baseline (speedup 1.0000x reference)
#include <cuda_runtime.h>

#define NN 200000

// Scratch (alloc-free: __device__ globals)
__device__ float  g_deg[NN];      // degree incl. self-loop
__device__ float  g_dis[NN];      // deg^{-1/2}
__device__ float2 g_xs[NN];       // x[i] * dis[i]           (layer-1 pre-scaled msg)
__device__ float2 g_aggx[NN];     // Sum of dis[s]*x[s] over in-edges + self
__device__ float4 g_zs[NN];       // z[i] * dis[i]           (layer-2 pre-scaled msg)

__device__ __forceinline__ void red_add_f32(float* p, float v) {
    asm volatile("red.global.add.f32 [%0], %1;" :: "l"(p), "f"(v) : "memory");
}
__device__ __forceinline__ void red_add_v2(float2* p, float a, float b) {
    asm volatile("red.global.add.v2.f32 [%0], {%1, %2};"
                 :: "l"(p), "f"(a), "f"(b) : "memory");
}
__device__ __forceinline__ void red_add_v4(float4* p, float a, float b, float c, float d) {
    asm volatile("red.global.add.v4.f32 [%0], {%1, %2, %3, %4};"
                 :: "l"(p), "f"(a), "f"(b), "f"(c), "f"(d) : "memory");
}

// --- 1. init degree with self-loop contribution ------------------------------
__global__ void k_init_deg(int n) {
    int i = blockIdx.x * blockDim.x + threadIdx.x;
    if (i < n) g_deg[i] = 1.0f;
}

// --- 2. count in-degree at dst ------------------------------------------------
__global__ void k_count_deg(const int* __restrict__ dst, int e) {
    int i = blockIdx.x * blockDim.x + threadIdx.x;
    if (i < e) red_add_f32(&g_deg[dst[i]], 1.0f);
}

// --- 3. per-node: dis, xs = x*dis, aggx init = self-loop term (= xs) ----------
__global__ void k_node1(const float2* __restrict__ x, int n) {
    int i = blockIdx.x * blockDim.x + threadIdx.x;
    if (i >= n) return;
    float dis = rsqrtf(g_deg[i]);
    g_dis[i] = dis;
    float2 xv = x[i];
    float2 xs = make_float2(xv.x * dis, xv.y * dis);
    g_xs[i]   = xs;
    g_aggx[i] = xs;   // self loop: norm = dis[i]^2, final dis[i] applied later
}

// --- 4. layer-1 edge scatter: pure gather(8B) + red(8B) -----------------------
__global__ void k_edge1(const int* __restrict__ src,
                        const int* __restrict__ dst, int e) {
    int i = blockIdx.x * blockDim.x + threadIdx.x;
    if (i >= e) return;
    int s = src[i], t = dst[i];
    float2 m = __ldg(&g_xs[s]);
    red_add_v2(&g_aggx[t], m.x, m.y);
}

// --- 5. per-node: full layer-1 (W1,b1,relu) + layer-2 transform (W2) ----------
__global__ void k_node2(const float* __restrict__ W1,
                        const float* __restrict__ b1,
                        const float* __restrict__ W2,
                        float4* __restrict__ out, int n) {
    int i = blockIdx.x * blockDim.x + threadIdx.x;
    if (i >= n) return;
    float dis = g_dis[i];
    float2 m = g_aggx[i];
    float m0 = m.x * dis, m1 = m.y * dis;
    float z[4] = {0.f, 0.f, 0.f, 0.f};
#pragma unroll
    for (int k = 0; k < 8; k++) {
        float v = fmaxf(fmaf(m0, __ldg(&W1[k]), fmaf(m1, __ldg(&W1[8 + k]), __ldg(&b1[k]))), 0.0f);
#pragma unroll
        for (int j = 0; j < 4; j++)
            z[j] = fmaf(v, __ldg(&W2[k * 4 + j]), z[j]);
    }
    float4 zs = make_float4(z[0] * dis, z[1] * dis, z[2] * dis, z[3] * dis);
    g_zs[i] = zs;
    out[i]  = zs;      // self-loop init for layer-2 aggregation
}

// --- 6. layer-2 edge scatter: gather(16B) + red(16B) into d_out ---------------
__global__ void k_edge2(const int* __restrict__ src,
                        const int* __restrict__ dst,
                        float4* __restrict__ out, int e) {
    int i = blockIdx.x * blockDim.x + threadIdx.x;
    if (i >= e) return;
    int s = src[i], t = dst[i];
    float4 m = __ldg(&g_zs[s]);
    red_add_v4(&out[t], m.x, m.y, m.z, m.w);
}

// --- 7. final dst scale + bias -------------------------------------------------
__global__ void k_final(const float* __restrict__ b2,
                        float4* __restrict__ out, int n) {
    int i = blockIdx.x * blockDim.x + threadIdx.x;
    if (i >= n) return;
    float dis = g_dis[i];
    float4 v = out[i];
    out[i] = make_float4(fmaf(v.x, dis, __ldg(&b2[0])),
                         fmaf(v.y, dis, __ldg(&b2[1])),
                         fmaf(v.z, dis, __ldg(&b2[2])),
                         fmaf(v.w, dis, __ldg(&b2[3])));
}

extern "C" void kernel_launch(void* const* d_in, const int* in_sizes, int n_in,
                              void* d_out, int out_size) {
    const float* x  = (const float*)d_in[0];
    const int*   ei = (const int*)d_in[1];
    const float* W1 = (const float*)d_in[2];
    const float* b1 = (const float*)d_in[3];
    const float* W2 = (const float*)d_in[4];
    const float* b2 = (const float*)d_in[5];
    float4* out = (float4*)d_out;

    int n = in_sizes[0] / 2;     // x is [N, 2]
    int e = in_sizes[1] / 2;     // edge_index is [2, E]
    const int* src = ei;
    const int* dst = ei + e;

    const int TB = 256;
    int nb_n = (n + TB - 1) / TB;
    int nb_e = (e + TB - 1) / TB;

    k_init_deg<<<nb_n, TB>>>(n);
    k_count_deg<<<nb_e, TB>>>(dst, e);
    k_node1<<<nb_n, TB>>>((const float2*)x, n);
    k_edge1<<<nb_e, TB>>>(src, dst, e);
    k_node2<<<nb_n, TB>>>(W1, b1, W2, out, n);
    k_edge2<<<nb_e, TB>>>(src, dst, out, e);
    k_final<<<nb_n, TB>>>(b2, out, n);
}

// round 15
// speedup vs baseline: 1.0380x; 1.0380x over previous
#include <cuda_runtime.h>

#define NN 200000

// Scratch (alloc-free: __device__ globals)
__device__ float  g_deg[NN];      // degree incl. self-loop
__device__ float  g_dis[NN];      // deg^{-1/2}
__device__ float2 g_xs[NN];       // x[i] * dis[i]           (layer-1 pre-scaled msg)
__device__ float2 g_aggx[NN];     // Sum of dis[s]*x[s] over in-edges + self
__device__ float4 g_zs[NN];       // z[i] * dis[i]           (layer-2 pre-scaled msg)

__device__ __forceinline__ void red_add_f32(float* p, float v) {
    asm volatile("red.global.add.f32 [%0], %1;" :: "l"(p), "f"(v) : "memory");
}
__device__ __forceinline__ void red_add_v2(float2* p, float a, float b) {
    asm volatile("red.global.add.v2.f32 [%0], {%1, %2};"
                 :: "l"(p), "f"(a), "f"(b) : "memory");
}
__device__ __forceinline__ void red_add_v4(float4* p, float a, float b, float c, float d) {
    asm volatile("red.global.add.v4.f32 [%0], {%1, %2, %3, %4};"
                 :: "l"(p), "f"(a), "f"(b), "f"(c), "f"(d) : "memory");
}

// --- 1. init degree with self-loop contribution ------------------------------
__global__ void k_init_deg(int n) {
    int i = blockIdx.x * blockDim.x + threadIdx.x;
    if (i < n) g_deg[i] = 1.0f;
}

// --- 2. count in-degree at dst ------------------------------------------------
__global__ void k_count_deg(const int* __restrict__ dst, int e) {
    int i = blockIdx.x * blockDim.x + threadIdx.x;
    if (i < e) red_add_f32(&g_deg[dst[i]], 1.0f);
}

// --- 3. per-node: dis, xs = x*dis, aggx init = self-loop term (= xs) ----------
__global__ void k_node1(const float2* __restrict__ x, int n) {
    int i = blockIdx.x * blockDim.x + threadIdx.x;
    if (i >= n) return;
    float dis = rsqrtf(g_deg[i]);
    g_dis[i] = dis;
    float2 xv = x[i];
    float2 xs = make_float2(xv.x * dis, xv.y * dis);
    g_xs[i]   = xs;
    g_aggx[i] = xs;   // self loop: norm = dis[i]^2, final dis[i] applied later
}

// --- 4. layer-1 edge scatter: pure gather(8B) + red(8B) -----------------------
__global__ void k_edge1(const int* __restrict__ src,
                        const int* __restrict__ dst, int e) {
    int i = blockIdx.x * blockDim.x + threadIdx.x;
    if (i >= e) return;
    int s = src[i], t = dst[i];
    float2 m = __ldg(&g_xs[s]);
    red_add_v2(&g_aggx[t], m.x, m.y);
}

// --- 5. per-node: full layer-1 (W1,b1,relu) + layer-2 transform (W2) ----------
__global__ void k_node2(const float* __restrict__ W1,
                        const float* __restrict__ b1,
                        const float* __restrict__ W2,
                        float4* __restrict__ out, int n) {
    int i = blockIdx.x * blockDim.x + threadIdx.x;
    if (i >= n) return;
    float dis = g_dis[i];
    float2 m = g_aggx[i];
    float m0 = m.x * dis, m1 = m.y * dis;
    float z[4] = {0.f, 0.f, 0.f, 0.f};
#pragma unroll
    for (int k = 0; k < 8; k++) {
        float v = fmaxf(fmaf(m0, __ldg(&W1[k]), fmaf(m1, __ldg(&W1[8 + k]), __ldg(&b1[k]))), 0.0f);
#pragma unroll
        for (int j = 0; j < 4; j++)
            z[j] = fmaf(v, __ldg(&W2[k * 4 + j]), z[j]);
    }
    float4 zs = make_float4(z[0] * dis, z[1] * dis, z[2] * dis, z[3] * dis);
    g_zs[i] = zs;
    out[i]  = zs;      // self-loop init for layer-2 aggregation
}

// --- 6. layer-2 edge scatter: gather(16B) + red(16B) into d_out ---------------
__global__ void k_edge2(const int* __restrict__ src,
                        const int* __restrict__ dst,
                        float4* __restrict__ out, int e) {
    int i = blockIdx.x * blockDim.x + threadIdx.x;
    if (i >= e) return;
    int s = src[i], t = dst[i];
    float4 m = __ldg(&g_zs[s]);
    red_add_v4(&out[t], m.x, m.y, m.z, m.w);
}

// --- 7. final dst scale + bias -------------------------------------------------
__global__ void k_final(const float* __restrict__ b2,
                        float4* __restrict__ out, int n) {
    int i = blockIdx.x * blockDim.x + threadIdx.x;
    if (i >= n) return;
    float dis = g_dis[i];
    float4 v = out[i];
    out[i] = make_float4(fmaf(v.x, dis, __ldg(&b2[0])),
                         fmaf(v.y, dis, __ldg(&b2[1])),
                         fmaf(v.z, dis, __ldg(&b2[2])),
                         fmaf(v.w, dis, __ldg(&b2[3])));
}

extern "C" void kernel_launch(void* const* d_in, const int* in_sizes, int n_in,
                              void* d_out, int out_size) {
    const float* x  = (const float*)d_in[0];
    const int*   ei = (const int*)d_in[1];
    const float* W1 = (const float*)d_in[2];
    const float* b1 = (const float*)d_in[3];
    const float* W2 = (const float*)d_in[4];
    const float* b2 = (const float*)d_in[5];
    float4* out = (float4*)d_out;

    int n = in_sizes[0] / 2;     // x is [N, 2]
    int e = in_sizes[1] / 2;     // edge_index is [2, E]
    const int* src = ei;
    const int* dst = ei + e;

    const int TB = 256;
    int nb_n = (n + TB - 1) / TB;
    int nb_e = (e + TB - 1) / TB;

    k_init_deg<<<nb_n, TB>>>(n);
    k_count_deg<<<nb_e, TB>>>(dst, e);
    k_node1<<<nb_n, TB>>>((const float2*)x, n);
    k_edge1<<<nb_e, TB>>>(src, dst, e);
    k_node2<<<nb_n, TB>>>(W1, b1, W2, out, n);
    k_edge2<<<nb_e, TB>>>(src, dst, out, e);
    k_final<<<nb_n, TB>>>(b2, out, n);
}

// round 16
// speedup vs baseline: 1.0465x; 1.0081x over previous
#include <cuda_runtime.h>

#define NN 200000

// Scratch (alloc-free: __device__ globals)
__device__ float  g_deg[NN];      // degree incl. self-loop
__device__ float  g_dis[NN];      // deg^{-1/2}
__device__ float2 g_xs[NN];       // x[i] * dis[i]           (layer-1 pre-scaled msg)
__device__ float2 g_aggx[NN];     // Sum of dis[s]*x[s] over in-edges + self
__device__ float4 g_zs[NN];       // z[i] * dis[i]           (layer-2 pre-scaled msg)

__device__ __forceinline__ void red_add_f32(float* p, float v) {
    asm volatile("red.global.add.f32 [%0], %1;" :: "l"(p), "f"(v) : "memory");
}
__device__ __forceinline__ void red_add_v2(float2* p, float a, float b) {
    asm volatile("red.global.add.v2.f32 [%0], {%1, %2};"
                 :: "l"(p), "f"(a), "f"(b) : "memory");
}
__device__ __forceinline__ void red_add_v4(float4* p, float a, float b, float c, float d) {
    asm volatile("red.global.add.v4.f32 [%0], {%1, %2, %3, %4};"
                 :: "l"(p), "f"(a), "f"(b), "f"(c), "f"(d) : "memory");
}

// --- 1. init degree with self-loop contribution ------------------------------
__global__ void k_init_deg(int n) {
    int i = blockIdx.x * blockDim.x + threadIdx.x;
    if (i < n) g_deg[i] = 1.0f;
}

// --- 2. count in-degree at dst ------------------------------------------------
__global__ void k_count_deg(const int* __restrict__ dst, int e) {
    int i = blockIdx.x * blockDim.x + threadIdx.x;
    if (i < e) red_add_f32(&g_deg[dst[i]], 1.0f);
}

// --- 3. per-node: dis, xs = x*dis, aggx init = self-loop term (= xs) ----------
__global__ void k_node1(const float2* __restrict__ x, int n) {
    int i = blockIdx.x * blockDim.x + threadIdx.x;
    if (i >= n) return;
    float dis = rsqrtf(g_deg[i]);
    g_dis[i] = dis;
    float2 xv = x[i];
    float2 xs = make_float2(xv.x * dis, xv.y * dis);
    g_xs[i]   = xs;
    g_aggx[i] = xs;   // self loop: norm = dis[i]^2, final dis[i] applied later
}

// --- 4. layer-1 edge scatter: pure gather(8B) + red(8B) -----------------------
__global__ void k_edge1(const int* __restrict__ src,
                        const int* __restrict__ dst, int e) {
    int i = blockIdx.x * blockDim.x + threadIdx.x;
    if (i >= e) return;
    int s = src[i], t = dst[i];
    float2 m = __ldg(&g_xs[s]);
    red_add_v2(&g_aggx[t], m.x, m.y);
}

// --- 5. per-node: full layer-1 (W1,b1,relu) + layer-2 transform (W2) ----------
__global__ void k_node2(const float* __restrict__ W1,
                        const float* __restrict__ b1,
                        const float* __restrict__ W2,
                        float4* __restrict__ out, int n) {
    int i = blockIdx.x * blockDim.x + threadIdx.x;
    if (i >= n) return;
    float dis = g_dis[i];
    float2 m = g_aggx[i];
    float m0 = m.x * dis, m1 = m.y * dis;
    float z[4] = {0.f, 0.f, 0.f, 0.f};
#pragma unroll
    for (int k = 0; k < 8; k++) {
        float v = fmaxf(fmaf(m0, __ldg(&W1[k]), fmaf(m1, __ldg(&W1[8 + k]), __ldg(&b1[k]))), 0.0f);
#pragma unroll
        for (int j = 0; j < 4; j++)
            z[j] = fmaf(v, __ldg(&W2[k * 4 + j]), z[j]);
    }
    float4 zs = make_float4(z[0] * dis, z[1] * dis, z[2] * dis, z[3] * dis);
    g_zs[i] = zs;
    out[i]  = zs;      // self-loop init for layer-2 aggregation
}

// --- 6. layer-2 edge scatter: gather(16B) + red(16B) into d_out ---------------
__global__ void k_edge2(const int* __restrict__ src,
                        const int* __restrict__ dst,
                        float4* __restrict__ out, int e) {
    int i = blockIdx.x * blockDim.x + threadIdx.x;
    if (i >= e) return;
    int s = src[i], t = dst[i];
    float4 m = __ldg(&g_zs[s]);
    red_add_v4(&out[t], m.x, m.y, m.z, m.w);
}

// --- 7. final dst scale + bias -------------------------------------------------
__global__ void k_final(const float* __restrict__ b2,
                        float4* __restrict__ out, int n) {
    int i = blockIdx.x * blockDim.x + threadIdx.x;
    if (i >= n) return;
    float dis = g_dis[i];
    float4 v = out[i];
    out[i] = make_float4(fmaf(v.x, dis, __ldg(&b2[0])),
                         fmaf(v.y, dis, __ldg(&b2[1])),
                         fmaf(v.z, dis, __ldg(&b2[2])),
                         fmaf(v.w, dis, __ldg(&b2[3])));
}

extern "C" void kernel_launch(void* const* d_in, const int* in_sizes, int n_in,
                              void* d_out, int out_size) {
    const float* x  = (const float*)d_in[0];
    const int*   ei = (const int*)d_in[1];
    const float* W1 = (const float*)d_in[2];
    const float* b1 = (const float*)d_in[3];
    const float* W2 = (const float*)d_in[4];
    const float* b2 = (const float*)d_in[5];
    float4* out = (float4*)d_out;

    int n = in_sizes[0] / 2;     // x is [N, 2]
    int e = in_sizes[1] / 2;     // edge_index is [2, E]
    const int* src = ei;
    const int* dst = ei + e;

    const int TB = 256;
    int nb_n = (n + TB - 1) / TB;
    int nb_e = (e + TB - 1) / TB;

    k_init_deg<<<nb_n, TB>>>(n);
    k_count_deg<<<nb_e, TB>>>(dst, e);
    k_node1<<<nb_n, TB>>>((const float2*)x, n);
    k_edge1<<<nb_e, TB>>>(src, dst, e);
    k_node2<<<nb_n, TB>>>(W1, b1, W2, out, n);
    k_edge2<<<nb_e, TB>>>(src, dst, out, e);
    k_final<<<nb_n, TB>>>(b2, out, n);
}